// round 7
// baseline (speedup 1.0000x reference)
#include <cuda_runtime.h>
#include <stdint.h>

// Problem constants (fixed shapes per reference_code)
#define NN 100000
#define EE 1600000
#define D  32
#define CHUNK 1024
#define NCH ((NN + CHUNK - 1) / CHUNK)   // 98
#define FULL 0xffffffffu

// ---------------- scratch (static device globals; no allocation) ----------------
__device__ int   g_deg[NN];
__device__ float g_dinv[NN];
__device__ int   g_rowptr[NN + 1];
__device__ int   g_bsum[NCH];
__device__ int   g_boff[NCH];
__device__ int   g_rank[EE];      // per-edge rank within its row (from hist atomic)
__device__ int2  g_cw[EE];        // per (CSR-sorted) edge: {col, float_bits(weight)}
__device__ float g_h [NN * D];    // layer-1 output
__device__ float g_t1[NN * D];    // Tx1

// ---------------- build kernels ----------------
__global__ void k_zero_deg() {
    int i = blockIdx.x * blockDim.x + threadIdx.x;
    if (i < NN) g_deg[i] = 0;
}

// edge_index arrives as int32; 4 edges per thread. The atomic's return value is
// the edge's rank within its row -> saved for an atomic-free scatter later.
__global__ void k_hist(const int4* __restrict__ ei4) {
    int t = blockIdx.x * blockDim.x + threadIdx.x;
    if (t < EE / 4) {
        int4 r = ei4[t];
        int4 c = ei4[EE / 4 + t];
        int e = t * 4;
        if (r.x != c.x) g_rank[e + 0] = atomicAdd(&g_deg[r.x], 1);
        if (r.y != c.y) g_rank[e + 1] = atomicAdd(&g_deg[r.y], 1);
        if (r.z != c.z) g_rank[e + 2] = atomicAdd(&g_deg[r.z], 1);
        if (r.w != c.w) g_rank[e + 3] = atomicAdd(&g_deg[r.w], 1);
    }
}

// ---- parallel 3-phase scan (phase 1 also emits dinv) ----
__global__ void __launch_bounds__(1024) k_scan1() {
    __shared__ int warp_sums[32];
    const int tid  = threadIdx.x;
    const int lane = tid & 31;
    const int wid  = tid >> 5;
    const int i    = blockIdx.x * CHUNK + tid;
    int v = (i < NN) ? g_deg[i] : 0;
    if (i < NN) g_dinv[i] = (v > 0) ? rsqrtf((float)v) : 0.0f;
    int incl = v;
    #pragma unroll
    for (int off = 1; off < 32; off <<= 1) {
        int t = __shfl_up_sync(FULL, incl, off);
        if (lane >= off) incl += t;
    }
    if (lane == 31) warp_sums[wid] = incl;
    __syncthreads();
    if (wid == 0) {
        int s  = warp_sums[lane];
        int si = s;
        #pragma unroll
        for (int off = 1; off < 32; off <<= 1) {
            int t = __shfl_up_sync(FULL, si, off);
            if (lane >= off) si += t;
        }
        warp_sums[lane] = si - s;
        if (lane == 31) g_bsum[blockIdx.x] = si;
    }
    __syncthreads();
    int excl = warp_sums[wid] + (incl - v);
    if (i < NN) g_rowptr[i] = excl;
}

__global__ void __launch_bounds__(128) k_scan2() {
    __shared__ int warp_sums[4];
    const int tid  = threadIdx.x;
    const int lane = tid & 31;
    const int wid  = tid >> 5;
    int v = (tid < NCH) ? g_bsum[tid] : 0;
    int incl = v;
    #pragma unroll
    for (int off = 1; off < 32; off <<= 1) {
        int t = __shfl_up_sync(FULL, incl, off);
        if (lane >= off) incl += t;
    }
    if (lane == 31) warp_sums[wid] = incl;
    __syncthreads();
    int carry = 0;
    #pragma unroll
    for (int w = 0; w < 4; w++)
        if (w < wid) carry += warp_sums[w];
    int excl = carry + incl - v;
    if (tid < NCH) g_boff[tid] = excl;
    if (tid == NCH - 1) g_rowptr[NN] = excl + v;
}

__global__ void __launch_bounds__(1024) k_scan3() {
    int i = blockIdx.x * CHUNK + threadIdx.x;
    if (i < NN) g_rowptr[i] += g_boff[blockIdx.x];
}

// Atomic-free scatter: pos = rowptr[row] + rank (rank captured in k_hist)
__global__ void k_scatter(const int4* __restrict__ ei4) {
    int t = blockIdx.x * blockDim.x + threadIdx.x;
    if (t < EE / 4) {
        int4 r = ei4[t];
        int4 c = ei4[EE / 4 + t];
        int e = t * 4;
        #pragma unroll
        for (int q = 0; q < 4; q++) {
            int rr = (q == 0) ? r.x : (q == 1) ? r.y : (q == 2) ? r.z : r.w;
            int cc = (q == 0) ? c.x : (q == 1) ? c.y : (q == 2) ? c.z : c.w;
            if (rr != cc) {
                int pos = g_rowptr[rr] + g_rank[e + q];
                float w = -g_dinv[rr] * g_dinv[cc];
                int2 cw;
                cw.x = cc;
                cw.y = __float_as_int(w);
                g_cw[pos] = cw;
            }
        }
    }
}

// ---------------- gather core (unroll 16) ----------------
// 8 lanes per edge: sub = lane>>3 picks edge within group-of-4, j = lane&7 picks
// the float4 feature chunk.
__device__ __forceinline__ float4 gather_row(int e0, int e1, int sub, int j,
                                             const float4* __restrict__ src4) {
    float4 acc = make_float4(0.f, 0.f, 0.f, 0.f);
    int e = e0 + sub;
    for (; e + 12 < e1; e += 16) {
        int2 a0 = g_cw[e];
        int2 a1 = g_cw[e + 4];
        int2 a2 = g_cw[e + 8];
        int2 a3 = g_cw[e + 12];
        float4 v0 = src4[a0.x * 8 + j];
        float4 v1 = src4[a1.x * 8 + j];
        float4 v2 = src4[a2.x * 8 + j];
        float4 v3 = src4[a3.x * 8 + j];
        float w0 = __int_as_float(a0.y);
        float w1 = __int_as_float(a1.y);
        float w2 = __int_as_float(a2.y);
        float w3 = __int_as_float(a3.y);
        acc.x = fmaf(w0, v0.x, acc.x); acc.y = fmaf(w0, v0.y, acc.y);
        acc.z = fmaf(w0, v0.z, acc.z); acc.w = fmaf(w0, v0.w, acc.w);
        acc.x = fmaf(w1, v1.x, acc.x); acc.y = fmaf(w1, v1.y, acc.y);
        acc.z = fmaf(w1, v1.z, acc.z); acc.w = fmaf(w1, v1.w, acc.w);
        acc.x = fmaf(w2, v2.x, acc.x); acc.y = fmaf(w2, v2.y, acc.y);
        acc.z = fmaf(w2, v2.z, acc.z); acc.w = fmaf(w2, v2.w, acc.w);
        acc.x = fmaf(w3, v3.x, acc.x); acc.y = fmaf(w3, v3.y, acc.y);
        acc.z = fmaf(w3, v3.z, acc.z); acc.w = fmaf(w3, v3.w, acc.w);
    }
    for (; e + 4 < e1; e += 8) {
        int2 a0 = g_cw[e];
        int2 a1 = g_cw[e + 4];
        float4 v0 = src4[a0.x * 8 + j];
        float4 v1 = src4[a1.x * 8 + j];
        float w0 = __int_as_float(a0.y);
        float w1 = __int_as_float(a1.y);
        acc.x = fmaf(w0, v0.x, acc.x); acc.y = fmaf(w0, v0.y, acc.y);
        acc.z = fmaf(w0, v0.z, acc.z); acc.w = fmaf(w0, v0.w, acc.w);
        acc.x = fmaf(w1, v1.x, acc.x); acc.y = fmaf(w1, v1.y, acc.y);
        acc.z = fmaf(w1, v1.z, acc.z); acc.w = fmaf(w1, v1.w, acc.w);
    }
    if (e < e1) {
        int2 a = g_cw[e];
        float4 v = src4[a.x * 8 + j];
        float w = __int_as_float(a.y);
        acc.x = fmaf(w, v.x, acc.x); acc.y = fmaf(w, v.y, acc.y);
        acc.z = fmaf(w, v.z, acc.z); acc.w = fmaf(w, v.w, acc.w);
    }
    return acc;
}

__device__ __forceinline__ void reduce_subs(float4& acc) {
    #pragma unroll
    for (int off = 8; off <= 16; off <<= 1) {
        acc.x += __shfl_xor_sync(FULL, acc.x, off);
        acc.y += __shfl_xor_sync(FULL, acc.y, off);
        acc.z += __shfl_xor_sync(FULL, acc.z, off);
        acc.w += __shfl_xor_sync(FULL, acc.w, off);
    }
}

// ---------------- prop1: dst = L_hat @ src ----------------
__global__ void __launch_bounds__(256) k_prop(const float4* __restrict__ src4,
                                              float4* __restrict__ dst4) {
    int row  = (blockIdx.x * blockDim.x + threadIdx.x) >> 5;
    int lane = threadIdx.x & 31;
    if (row >= NN) return;
    int sub = lane >> 3, j = lane & 7;
    int e0 = g_rowptr[row], e1 = g_rowptr[row + 1];
    float4 acc = gather_row(e0, e1, sub, j, src4);
    reduce_subs(acc);
    if (lane < 8) dst4[row * 8 + lane] = acc;   // lane == j here
}

// ---------------- fused prop2 + epilogue (shuffle-free GEMV) ----------------
// p = L_hat @ t1, then out = h0@(W0-W2) + t1@W1 + p@(2*W2) + b.
// Row broadcasts come from uniform-address LDG.128 (h0, t1) and a per-warp
// double-buffered smem slot (p), replacing 96 SHFLs per row.
__global__ void __launch_bounds__(256, 2) k_prop_epi(
        const float4* __restrict__ t1v,      // t1 rows (gather source + broadcast)
        const float4* __restrict__ h4,       // Tx0 rows as float4
        const float*  __restrict__ W,        // (3, 32, 32)
        const float*  __restrict__ b,
        const float*  __restrict__ resid,    // nullptr or residual rows
        float*        __restrict__ out,
        int do_relu) {
    __shared__ float4 pbuf[8][2][8];         // [warp][buffer][chunk]
    const int lane = threadIdx.x & 31;
    const int warp = threadIdx.x >> 5;
    const int sub  = lane >> 3, j = lane & 7;
    const int gw   = (blockIdx.x * blockDim.x + threadIdx.x) >> 5;
    const int tot  = (gridDim.x * blockDim.x) >> 5;

    // per-lane weight columns in registers (output col = lane)
    float wc[D], w1[D], w2[D];
    #pragma unroll
    for (int i = 0; i < D; i++) {
        float a0 = W[i * D + lane];
        float a1 = W[D * D + i * D + lane];
        float a2 = W[2 * D * D + i * D + lane];
        wc[i] = a0 - a2;
        w1[i] = a1;
        w2[i] = 2.0f * a2;
    }
    const float bias = b[lane];

    int buf = 0;
    for (int row = gw; row < NN; row += tot) {
        int e0 = g_rowptr[row], e1 = g_rowptr[row + 1];
        float4 acc = gather_row(e0, e1, sub, j, t1v);
        reduce_subs(acc);                    // lanes 0..7 hold chunk j = lane
        if (lane < 8) pbuf[warp][buf][lane] = acc;
        __syncwarp();
        float o = bias;
        #pragma unroll
        for (int i4 = 0; i4 < 8; i4++) {
            float4 hv = h4 [row * 8 + i4];   // uniform address -> HW broadcast
            float4 tv = t1v[row * 8 + i4];
            float4 pv = pbuf[warp][buf][i4]; // broadcast LDS
            o = fmaf(hv.x, wc[4*i4+0], o); o = fmaf(hv.y, wc[4*i4+1], o);
            o = fmaf(hv.z, wc[4*i4+2], o); o = fmaf(hv.w, wc[4*i4+3], o);
            o = fmaf(tv.x, w1[4*i4+0], o); o = fmaf(tv.y, w1[4*i4+1], o);
            o = fmaf(tv.z, w1[4*i4+2], o); o = fmaf(tv.w, w1[4*i4+3], o);
            o = fmaf(pv.x, w2[4*i4+0], o); o = fmaf(pv.y, w2[4*i4+1], o);
            o = fmaf(pv.z, w2[4*i4+2], o); o = fmaf(pv.w, w2[4*i4+3], o);
        }
        if (do_relu) o = fmaxf(o, 0.0f);
        if (resid)   o += resid[row * D + lane];
        out[row * D + lane] = o;
        buf ^= 1;                            // double buffer: 1 syncwarp per row
    }
}

// ---------------- launch ----------------
extern "C" void kernel_launch(void* const* d_in, const int* in_sizes, int n_in,
                              void* d_out, int out_size) {
    const float* x  = (const float*)d_in[0];
    const int*   ei = (const int*)d_in[1];       // int32 edge_index (2, E)
    const float* W1 = (const float*)d_in[2];
    const float* b1 = (const float*)d_in[3];
    const float* W2 = (const float*)d_in[4];
    const float* b2 = (const float*)d_in[5];
    float*       out = (float*)d_out;

    float *p_h, *p_t1;
    cudaGetSymbolAddress((void**)&p_h,  g_h);
    cudaGetSymbolAddress((void**)&p_t1, g_t1);

    const int TB = 256;
    int gN  = (NN + TB - 1) / TB;
    int gE4 = (EE / 4 + TB - 1) / TB;
    int gProp = (NN + 7) / 8;          // one warp per row
    int gFuse = 296;                   // 148 SMs * 2 resident CTAs

    // ---- CSR build ----
    k_zero_deg<<<gN, TB>>>();
    k_hist<<<gE4, TB>>>((const int4*)ei);
    k_scan1<<<NCH, 1024>>>();
    k_scan2<<<1, 128>>>();
    k_scan3<<<NCH, 1024>>>();
    k_scatter<<<gE4, TB>>>((const int4*)ei);

    // ---- layer 1: h = relu(cheb(x; W1,b1)) ----
    k_prop<<<gProp, TB>>>((const float4*)x, (float4*)p_t1);
    k_prop_epi<<<gFuse, TB>>>((const float4*)p_t1, (const float4*)x, W1, b1,
                              (const float*)nullptr, p_h, 1);

    // ---- layer 2 + residual: out = cheb(h; W2,b2) + x ----
    k_prop<<<gProp, TB>>>((const float4*)p_h, (float4*)p_t1);
    k_prop_epi<<<gFuse, TB>>>((const float4*)p_t1, (const float4*)p_h, W2, b2,
                              x, out, 0);
}

// round 8
// speedup vs baseline: 1.1497x; 1.1497x over previous
#include <cuda_runtime.h>
#include <stdint.h>

// Problem constants (fixed shapes per reference_code)
#define NN 100000
#define EE 1600000
#define D  32
#define CHUNK 1024
#define NCH ((NN + CHUNK - 1) / CHUNK)   // 98
#define FULL 0xffffffffu

// ---------------- scratch (static device globals; no allocation) ----------------
__device__ int   g_deg[NN];
__device__ float g_dinv[NN];     // 1/sqrt(deg) (0 if deg==0)
__device__ float g_sd[NN];       // sqrt(deg)
__device__ int   g_rowptr[NN + 1];
__device__ int   g_bsum[NCH];
__device__ int   g_boff[NCH];
__device__ int   g_rank[EE];     // per-edge rank within its row (from hist atomic)
__device__ int   g_col[EE];      // CSR column index only (no weight needed!)
__device__ float g_xs[NN * D];   // dinv-scaled x (layer-1 gather source)
__device__ float g_h [NN * D];   // layer-1 output (true values)
__device__ float g_hs[NN * D];   // dinv-scaled h (layer-2 gather source)
__device__ float g_t1[NN * D];   // Tx1 in SCALED space (dinv * true)

// ---------------- build kernels ----------------
__global__ void k_zero_deg() {
    int i = blockIdx.x * blockDim.x + threadIdx.x;
    if (i < NN) g_deg[i] = 0;
}

// edge_index arrives as int32; 4 edges per thread. The atomic's return value is
// the edge's rank within its row -> saved for an atomic-free scatter later.
__global__ void k_hist(const int4* __restrict__ ei4) {
    int t = blockIdx.x * blockDim.x + threadIdx.x;
    if (t < EE / 4) {
        int4 r = ei4[t];
        int4 c = ei4[EE / 4 + t];
        int e = t * 4;
        if (r.x != c.x) g_rank[e + 0] = atomicAdd(&g_deg[r.x], 1);
        if (r.y != c.y) g_rank[e + 1] = atomicAdd(&g_deg[r.y], 1);
        if (r.z != c.z) g_rank[e + 2] = atomicAdd(&g_deg[r.z], 1);
        if (r.w != c.w) g_rank[e + 3] = atomicAdd(&g_deg[r.w], 1);
    }
}

// ---- parallel 3-phase scan (phase 1 also emits dinv & sqrt(deg)) ----
__global__ void __launch_bounds__(1024) k_scan1() {
    __shared__ int warp_sums[32];
    const int tid  = threadIdx.x;
    const int lane = tid & 31;
    const int wid  = tid >> 5;
    const int i    = blockIdx.x * CHUNK + tid;
    int v = (i < NN) ? g_deg[i] : 0;
    if (i < NN) {
        g_dinv[i] = (v > 0) ? rsqrtf((float)v) : 0.0f;
        g_sd[i]   = sqrtf((float)v);
    }
    int incl = v;
    #pragma unroll
    for (int off = 1; off < 32; off <<= 1) {
        int t = __shfl_up_sync(FULL, incl, off);
        if (lane >= off) incl += t;
    }
    if (lane == 31) warp_sums[wid] = incl;
    __syncthreads();
    if (wid == 0) {
        int s  = warp_sums[lane];
        int si = s;
        #pragma unroll
        for (int off = 1; off < 32; off <<= 1) {
            int t = __shfl_up_sync(FULL, si, off);
            if (lane >= off) si += t;
        }
        warp_sums[lane] = si - s;
        if (lane == 31) g_bsum[blockIdx.x] = si;
    }
    __syncthreads();
    int excl = warp_sums[wid] + (incl - v);
    if (i < NN) g_rowptr[i] = excl;
}

__global__ void __launch_bounds__(128) k_scan2() {
    __shared__ int warp_sums[4];
    const int tid  = threadIdx.x;
    const int lane = tid & 31;
    const int wid  = tid >> 5;
    int v = (tid < NCH) ? g_bsum[tid] : 0;
    int incl = v;
    #pragma unroll
    for (int off = 1; off < 32; off <<= 1) {
        int t = __shfl_up_sync(FULL, incl, off);
        if (lane >= off) incl += t;
    }
    if (lane == 31) warp_sums[wid] = incl;
    __syncthreads();
    int carry = 0;
    #pragma unroll
    for (int w = 0; w < 4; w++)
        if (w < wid) carry += warp_sums[w];
    int excl = carry + incl - v;
    if (tid < NCH) g_boff[tid] = excl;
    if (tid == NCH - 1) g_rowptr[NN] = excl + v;
}

__global__ void __launch_bounds__(1024) k_scan3() {
    int i = blockIdx.x * CHUNK + threadIdx.x;
    if (i < NN) g_rowptr[i] += g_boff[blockIdx.x];
}

// Atomic-free scatter: pos = rowptr[row] + rank. Writes ONLY the column index —
// no weight computation, no random dinv[col] reads.
__global__ void k_scatter(const int4* __restrict__ ei4) {
    int t = blockIdx.x * blockDim.x + threadIdx.x;
    if (t < EE / 4) {
        int4 r = ei4[t];
        int4 c = ei4[EE / 4 + t];
        int e = t * 4;
        #pragma unroll
        for (int q = 0; q < 4; q++) {
            int rr = (q == 0) ? r.x : (q == 1) ? r.y : (q == 2) ? r.z : r.w;
            int cc = (q == 0) ? c.x : (q == 1) ? c.y : (q == 2) ? c.z : c.w;
            if (rr != cc) g_col[g_rowptr[rr] + g_rank[e + q]] = cc;
        }
    }
}

// ---- x_scaled = dinv ⊙ x : coalesced elementwise (8 float4 per node) ----
__global__ void __launch_bounds__(256) k_pre(const float4* __restrict__ x4) {
    int t = blockIdx.x * blockDim.x + threadIdx.x;
    if (t < NN * 8) {
        float d = g_dinv[t >> 3];
        float4 v = x4[t];
        v.x *= d; v.y *= d; v.z *= d; v.w *= d;
        ((float4*)g_xs)[t] = v;
    }
}

// ---------------- gather core (col-only, unroll 16) ----------------
// 8 lanes per edge: sub = lane>>3 picks edge within group-of-4, j = lane&7 picks
// the float4 feature chunk. Source rows are PRE-SCALED by dinv -> plain adds.
__device__ __forceinline__ float4 gather_row(int e0, int e1, int sub, int j,
                                             const float4* __restrict__ src4) {
    float4 acc = make_float4(0.f, 0.f, 0.f, 0.f);
    int e = e0 + sub;
    for (; e + 12 < e1; e += 16) {
        int c0 = g_col[e];
        int c1 = g_col[e + 4];
        int c2 = g_col[e + 8];
        int c3 = g_col[e + 12];
        float4 v0 = src4[c0 * 8 + j];
        float4 v1 = src4[c1 * 8 + j];
        float4 v2 = src4[c2 * 8 + j];
        float4 v3 = src4[c3 * 8 + j];
        acc.x += v0.x; acc.y += v0.y; acc.z += v0.z; acc.w += v0.w;
        acc.x += v1.x; acc.y += v1.y; acc.z += v1.z; acc.w += v1.w;
        acc.x += v2.x; acc.y += v2.y; acc.z += v2.z; acc.w += v2.w;
        acc.x += v3.x; acc.y += v3.y; acc.z += v3.z; acc.w += v3.w;
    }
    for (; e + 4 < e1; e += 8) {
        int c0 = g_col[e];
        int c1 = g_col[e + 4];
        float4 v0 = src4[c0 * 8 + j];
        float4 v1 = src4[c1 * 8 + j];
        acc.x += v0.x; acc.y += v0.y; acc.z += v0.z; acc.w += v0.w;
        acc.x += v1.x; acc.y += v1.y; acc.z += v1.z; acc.w += v1.w;
    }
    if (e < e1) {
        int c = g_col[e];
        float4 v = src4[c * 8 + j];
        acc.x += v.x; acc.y += v.y; acc.z += v.z; acc.w += v.w;
    }
    return acc;
}

__device__ __forceinline__ void reduce_subs(float4& acc) {
    #pragma unroll
    for (int off = 8; off <= 16; off <<= 1) {
        acc.x += __shfl_xor_sync(FULL, acc.x, off);
        acc.y += __shfl_xor_sync(FULL, acc.y, off);
        acc.z += __shfl_xor_sync(FULL, acc.z, off);
        acc.w += __shfl_xor_sync(FULL, acc.w, off);
    }
}

// ---------------- prop1: t1_scaled = dinv ⊙ (L_hat @ src_true) ----------------
// src is SCALED; true result = -dinv[row]*acc; stored scaled = -dinv^2*acc.
__global__ void __launch_bounds__(256) k_prop(const float4* __restrict__ src4,
                                              float4* __restrict__ dst4) {
    int row  = (blockIdx.x * blockDim.x + threadIdx.x) >> 5;
    int lane = threadIdx.x & 31;
    if (row >= NN) return;
    int sub = lane >> 3, j = lane & 7;
    int e0 = g_rowptr[row], e1 = g_rowptr[row + 1];
    float4 acc = gather_row(e0, e1, sub, j, src4);
    reduce_subs(acc);
    float di = g_dinv[row];
    float s  = -di * di;
    if (lane < 8) {
        acc.x *= s; acc.y *= s; acc.z *= s; acc.w *= s;
        dst4[row * 8 + lane] = acc;   // lane == j here
    }
}

// ---------------- fused prop2 + epilogue (R6 shfl epilogue) ----------------
// p_true = -dinv[row] * (sum of scaled t1 over cols);
// t1_true = t1_scaled * sqrt(deg);  out = h0@(W0-W2) + t1@W1 + p@(2W2) + b
__global__ void __launch_bounds__(256, 2) k_prop_epi(
        const float4* __restrict__ t1v,      // t1 SCALED (gather source)
        const float*  __restrict__ t1,       // t1 SCALED scalar view
        const float*  __restrict__ h0,       // Tx0 rows (true)
        const float*  __restrict__ W,        // (3, 32, 32)
        const float*  __restrict__ b,
        const float*  __restrict__ resid,    // nullptr or residual rows
        float*        __restrict__ out,      // true output
        float*        __restrict__ outs,     // nullptr or dinv-scaled copy
        int do_relu) {
    const int lane = threadIdx.x & 31;
    const int sub  = lane >> 3, j = lane & 7;
    const int gw   = (blockIdx.x * blockDim.x + threadIdx.x) >> 5;
    const int tot  = (gridDim.x * blockDim.x) >> 5;

    // per-lane weight columns in registers
    float wc[D], w1[D], w2[D];
    #pragma unroll
    for (int i = 0; i < D; i++) {
        float a0 = W[i * D + lane];
        float a1 = W[D * D + i * D + lane];
        float a2 = W[2 * D * D + i * D + lane];
        wc[i] = a0 - a2;
        w1[i] = a1;
        w2[i] = 2.0f * a2;
    }
    const float bias = b[lane];

    for (int row = gw; row < NN; row += tot) {
        int e0 = g_rowptr[row], e1 = g_rowptr[row + 1];
        float4 acc = gather_row(e0, e1, sub, j, t1v);
        reduce_subs(acc);                 // all lanes: scaled-p chunk for j = lane&7
        float di = g_dinv[row];
        float sd = g_sd[row];
        float nd = -di;
        acc.x *= nd; acc.y *= nd; acc.z *= nd; acc.w *= nd;   // p_true chunk
        float hv = h0[row * D + lane];
        float tv = t1[row * D + lane] * sd;                    // unscale t1
        float o = bias;
        #pragma unroll
        for (int i = 0; i < D; i++) {
            float hi = __shfl_sync(FULL, hv, i);
            float ti = __shfl_sync(FULL, tv, i);
            float comp = ((i & 3) == 0) ? acc.x :
                         ((i & 3) == 1) ? acc.y :
                         ((i & 3) == 2) ? acc.z : acc.w;
            float pi = __shfl_sync(FULL, comp, i >> 2);
            o = fmaf(hi, wc[i], o);
            o = fmaf(ti, w1[i], o);
            o = fmaf(pi, w2[i], o);
        }
        if (do_relu) o = fmaxf(o, 0.0f);
        if (resid)   o += resid[row * D + lane];
        out[row * D + lane] = o;
        if (outs) outs[row * D + lane] = di * o;   // scaled copy for next gather
    }
}

// ---------------- launch ----------------
extern "C" void kernel_launch(void* const* d_in, const int* in_sizes, int n_in,
                              void* d_out, int out_size) {
    const float* x  = (const float*)d_in[0];
    const int*   ei = (const int*)d_in[1];       // int32 edge_index (2, E)
    const float* W1 = (const float*)d_in[2];
    const float* b1 = (const float*)d_in[3];
    const float* W2 = (const float*)d_in[4];
    const float* b2 = (const float*)d_in[5];
    float*       out = (float*)d_out;

    float *p_xs, *p_h, *p_hs, *p_t1;
    cudaGetSymbolAddress((void**)&p_xs, g_xs);
    cudaGetSymbolAddress((void**)&p_h,  g_h);
    cudaGetSymbolAddress((void**)&p_hs, g_hs);
    cudaGetSymbolAddress((void**)&p_t1, g_t1);

    const int TB = 256;
    int gN  = (NN + TB - 1) / TB;
    int gE4 = (EE / 4 + TB - 1) / TB;
    int gV  = (NN * 8 + TB - 1) / TB;  // float4 elementwise
    int gProp = (NN + 7) / 8;          // one warp per row
    int gFuse = 296;                   // 148 SMs * 2 resident CTAs

    // ---- CSR build (col-only) ----
    k_zero_deg<<<gN, TB>>>();
    k_hist<<<gE4, TB>>>((const int4*)ei);
    k_scan1<<<NCH, 1024>>>();
    k_scan2<<<1, 128>>>();
    k_scan3<<<NCH, 1024>>>();
    k_scatter<<<gE4, TB>>>((const int4*)ei);
    k_pre<<<gV, TB>>>((const float4*)x);

    // ---- layer 1: h = relu(cheb(x; W1,b1)), plus scaled copy hs ----
    k_prop<<<gProp, TB>>>((const float4*)p_xs, (float4*)p_t1);
    k_prop_epi<<<gFuse, TB>>>((const float4*)p_t1, p_t1, x, W1, b1,
                              (const float*)nullptr, p_h, p_hs, 1);

    // ---- layer 2 + residual: out = cheb(h; W2,b2) + x ----
    k_prop<<<gProp, TB>>>((const float4*)p_hs, (float4*)p_t1);
    k_prop_epi<<<gFuse, TB>>>((const float4*)p_t1, p_t1, p_h, W2, b2,
                              x, out, (float*)nullptr, 0);
}